// round 5
// baseline (speedup 1.0000x reference)
#include <cuda_runtime.h>

// Problem constants
#define B_   32
#define K_   8
#define LQ_  128
#define LR_  256
#define H_   512
#define L_   2176          // LQ + K*LR
#define BKT  256           // B*K
#define NQROWS 4096        // B*LQ
#define NRROWS 65536       // B*K*LR

// -------- scratch (device globals; no runtime allocation) --------
__device__ float g_hqU[NQROWS * H_];          // 8 MB
__device__ float g_Yq [NQROWS * H_];          // 8 MB
__device__ float g_Yr [(size_t)NRROWS * H_];  // 128 MB
__device__ float g_rowmax[BKT * 4 * LQ_];
__device__ float g_colmax[BKT * LR_];
__device__ float g_alpha_q[BKT * LQ_];
__device__ float g_scale[B_ * L_];
__device__ float g_Ss[B_ * H_];
__device__ float g_logits[B_ * L_];

// Precise tanh, robust under --use_fast_math.
// tanh(x) = sign(x) * (1 - e^{-2|x|}) / (1 + e^{-2|x|}); expf arg <= 0 -> no overflow.
__device__ __forceinline__ float precise_tanh(float x) {
    const float ax = fabsf(x);
    const float e  = expf(-2.0f * ax);
    const float r  = (1.0f - e) / (1.0f + e);
    return copysignf(r, x);
}

// ================================================================
// C[M,512] = A[M,512] @ W^T, W stored [o][i] (torch-style [out,in])
// 128x128 block tile, BK=8, 256 threads, 8x8 microtile.
// dst selects the __device__ global destination (resolved in device code!):
//   0 -> g_hqU, 1 -> g_Yq, 2 -> g_Yr
// ================================================================
__global__ __launch_bounds__(256) void sgemm_nt_kernel(
    const float* __restrict__ A, const float* __restrict__ W, int dst)
{
    float* C = (dst == 0) ? g_hqU : (dst == 1) ? g_Yq : g_Yr;

    __shared__ float As[8][128];
    __shared__ float Bs[8][128];
    const int tid = threadIdx.x;
    const size_t bm = (size_t)blockIdx.y * 128;
    const int    bn = blockIdx.x * 128;
    const int lr = tid >> 1;
    const int lc = (tid & 1) << 2;
    const int tr = (tid >> 4) << 3;
    const int tc = (tid & 15) << 3;

    float acc[8][8];
#pragma unroll
    for (int i = 0; i < 8; i++)
#pragma unroll
        for (int j = 0; j < 8; j++) acc[i][j] = 0.f;

    const float* Ap = A + (bm + lr) * H_ + lc;
    const float* Wp = W + (size_t)(bn + lr) * H_ + lc;

    for (int k0 = 0; k0 < H_; k0 += 8) {
        float4 av = *(const float4*)(Ap + k0);
        float4 wv = *(const float4*)(Wp + k0);
        As[lc + 0][lr] = av.x; As[lc + 1][lr] = av.y;
        As[lc + 2][lr] = av.z; As[lc + 3][lr] = av.w;
        Bs[lc + 0][lr] = wv.x; Bs[lc + 1][lr] = wv.y;
        Bs[lc + 2][lr] = wv.z; Bs[lc + 3][lr] = wv.w;
        __syncthreads();
#pragma unroll
        for (int kk = 0; kk < 8; kk++) {
            float ar[8], br[8];
#pragma unroll
            for (int i = 0; i < 8; i++) ar[i] = As[kk][tr + i];
#pragma unroll
            for (int j = 0; j < 8; j++) br[j] = Bs[kk][tc + j];
#pragma unroll
            for (int i = 0; i < 8; i++)
#pragma unroll
                for (int j = 0; j < 8; j++)
                    acc[i][j] = fmaf(ar[i], br[j], acc[i][j]);
        }
        __syncthreads();
    }
#pragma unroll
    for (int i = 0; i < 8; i++) {
        float4* crow = (float4*)(C + (bm + tr + i) * H_ + bn + tc);
        crow[0] = make_float4(acc[i][0], acc[i][1], acc[i][2], acc[i][3]);
        crow[1] = make_float4(acc[i][4], acc[i][5], acc[i][6], acc[i][7]);
    }
}

// ================================================================
// Scores: for (bk, r-tile): U = tanh(hqU[b] @ h_r[b,k]^T) on a
// 128(q) x 64(r) tile; keep only row/col maxes. Never stores U.
// ================================================================
__global__ __launch_bounds__(256) void scores_kernel(
    const float* __restrict__ h_r)
{
    __shared__ float As[8][128];
    __shared__ float Bs[8][64];
    __shared__ float redQ[16][128];
    __shared__ float redC[16][64];

    const int bk = blockIdx.y;           // 0..255
    const int rt = blockIdx.x;           // 0..3
    const int b  = bk >> 3;
    const int tid = threadIdx.x;
    const int lr = tid >> 1;
    const int lc = (tid & 1) << 2;
    const int tr = (tid >> 4) << 3;      // q offset
    const int tc = (tid & 15) << 2;      // r offset (0..60)

    const float* A  = g_hqU + (size_t)b * LQ_ * H_;
    const float* Bp = h_r + ((size_t)bk * LR_ + rt * 64) * H_;

    float acc[8][4];
#pragma unroll
    for (int i = 0; i < 8; i++)
#pragma unroll
        for (int j = 0; j < 4; j++) acc[i][j] = 0.f;

    for (int k0 = 0; k0 < H_; k0 += 8) {
        float4 av = *(const float4*)(A + (size_t)lr * H_ + k0 + lc);
        As[lc + 0][lr] = av.x; As[lc + 1][lr] = av.y;
        As[lc + 2][lr] = av.z; As[lc + 3][lr] = av.w;
        if (tid < 128) {
            float4 bv = *(const float4*)(Bp + (size_t)lr * H_ + k0 + lc);
            Bs[lc + 0][lr] = bv.x; Bs[lc + 1][lr] = bv.y;
            Bs[lc + 2][lr] = bv.z; Bs[lc + 3][lr] = bv.w;
        }
        __syncthreads();
#pragma unroll
        for (int kk = 0; kk < 8; kk++) {
            float ar[8], br[4];
#pragma unroll
            for (int i = 0; i < 8; i++) ar[i] = As[kk][tr + i];
#pragma unroll
            for (int j = 0; j < 4; j++) br[j] = Bs[kk][tc + j];
#pragma unroll
            for (int i = 0; i < 8; i++)
#pragma unroll
                for (int j = 0; j < 4; j++)
                    acc[i][j] = fmaf(ar[i], br[j], acc[i][j]);
        }
        __syncthreads();
    }

    // local maxes of raw scores (tanh monotonic: tanh applied after max)
    float rmax[8], cmax[4];
#pragma unroll
    for (int i = 0; i < 8; i++) rmax[i] = -1e30f;
#pragma unroll
    for (int j = 0; j < 4; j++) cmax[j] = -1e30f;
#pragma unroll
    for (int i = 0; i < 8; i++)
#pragma unroll
        for (int j = 0; j < 4; j++) {
            float u = acc[i][j];
            rmax[i] = fmaxf(rmax[i], u);
            cmax[j] = fmaxf(cmax[j], u);
        }
    const int txg = tid & 15;
    const int tyg = tid >> 4;
#pragma unroll
    for (int i = 0; i < 8; i++) redQ[txg][tr + i] = rmax[i];
#pragma unroll
    for (int j = 0; j < 4; j++) redC[tyg][tc + j] = cmax[j];
    __syncthreads();

    if (tid < 128) {
        float m = -1e30f;
#pragma unroll
        for (int g = 0; g < 16; g++) m = fmaxf(m, redQ[g][tid]);
        g_rowmax[((size_t)bk * 4 + rt) * LQ_ + tid] = precise_tanh(m);
    } else if (tid < 192) {
        int r = tid - 128;
        float m = -1e30f;
#pragma unroll
        for (int g = 0; g < 16; g++) m = fmaxf(m, redC[g][r]);
        g_colmax[(size_t)bk * LR_ + rt * 64 + r] = precise_tanh(m);
    }
}

// ---------- softmax over q of rowmax -> alpha_q ----------
__global__ __launch_bounds__(128) void alphaq_kernel()
{
    const int bk = blockIdx.x;
    const int q  = threadIdx.x;
    float m = g_rowmax[(bk * 4 + 0) * LQ_ + q];
    m = fmaxf(m, g_rowmax[(bk * 4 + 1) * LQ_ + q]);
    m = fmaxf(m, g_rowmax[(bk * 4 + 2) * LQ_ + q]);
    m = fmaxf(m, g_rowmax[(bk * 4 + 3) * LQ_ + q]);
    __shared__ float red[128];
    red[q] = m; __syncthreads();
    for (int s = 64; s > 0; s >>= 1) {
        if (q < s) red[q] = fmaxf(red[q], red[q + s]);
        __syncthreads();
    }
    const float mx = red[0]; __syncthreads();
    const float e = expf(m - mx);
    red[q] = e; __syncthreads();
    for (int s = 64; s > 0; s >>= 1) {
        if (q < s) red[q] += red[q + s];
        __syncthreads();
    }
    g_alpha_q[bk * LQ_ + q] = e / red[0];
}

// ---------- scale for q rows: mean over k ----------
__global__ __launch_bounds__(128) void scaleq_kernel(const float* __restrict__ q_mask)
{
    const int b = blockIdx.x, q = threadIdx.x;
    float s = 0.f;
#pragma unroll
    for (int k = 0; k < K_; k++) s += g_alpha_q[(b * K_ + k) * LQ_ + q];
    g_scale[b * L_ + q] = s * 0.125f * q_mask[b * LQ_ + q];
}

// ---------- softmax over r of colmax -> scale for r rows ----------
__global__ __launch_bounds__(256) void alphar_kernel(const float* __restrict__ r_mask)
{
    const int bk = blockIdx.x;
    const int r  = threadIdx.x;
    const float m = g_colmax[(size_t)bk * LR_ + r];
    __shared__ float red[256];
    red[r] = m; __syncthreads();
    for (int s = 128; s > 0; s >>= 1) {
        if (r < s) red[r] = fmaxf(red[r], red[r + s]);
        __syncthreads();
    }
    const float mx = red[0]; __syncthreads();
    const float e = expf(m - mx);
    red[r] = e; __syncthreads();
    for (int s = 128; s > 0; s >>= 1) {
        if (r < s) red[r] += red[r + s];
        __syncthreads();
    }
    const int b = bk >> 3, k = bk & 7;
    g_scale[b * L_ + LQ_ + k * LR_ + r] = (e / red[0]) * r_mask[(size_t)bk * LR_ + r];
}

// ---------- Ss = s_t @ Ws^T ----------
__global__ __launch_bounds__(512) void ss_kernel(
    const float* __restrict__ s_t, const float* __restrict__ Ws)
{
    const int b = blockIdx.x, o = threadIdx.x;
    __shared__ float sv[H_];
    sv[o] = s_t[b * H_ + o];
    __syncthreads();
    const float* w = Ws + (size_t)o * H_;
    float acc = 0.f;
#pragma unroll 8
    for (int i = 0; i < H_; i++) acc = fmaf(sv[i], w[i], acc);
    g_Ss[b * H_ + o] = acc;
}

// ---------- logits: one warp per (b,l) row ----------
__global__ __launch_bounds__(256) void logits_kernel(
    const float* __restrict__ qr_cov, const float* __restrict__ Wqr_b,
    const float* __restrict__ Wc, const float* __restrict__ Vr)
{
    const int gw   = (blockIdx.x * 256 + threadIdx.x) >> 5;
    const int lane = threadIdx.x & 31;
    if (gw >= B_ * L_) return;
    const int b = gw / L_;
    const int l = gw - b * L_;
    const float* Y = (l < LQ_)
        ? (g_Yq + ((size_t)b * LQ_ + l) * H_)
        : (g_Yr + ((size_t)b * (K_ * LR_) + (l - LQ_)) * H_);
    const float sc  = g_scale[gw];
    const float cov = qr_cov[gw];
    const float* ss = g_Ss + b * H_;
    float acc = 0.f;
#pragma unroll
    for (int t = 0; t < 16; t++) {
        const int o = lane + t * 32;
        const float d = ss[o] + sc * Y[o] + Wqr_b[o] + cov * Wc[o];
        acc += Vr[o] * precise_tanh(d);
    }
#pragma unroll
    for (int s = 16; s > 0; s >>= 1) acc += __shfl_xor_sync(0xffffffffu, acc, s);
    if (lane == 0) g_logits[gw] = acc;
}

// ---------- final masked softmax over L, write a & new_cov ----------
__global__ __launch_bounds__(256) void final_softmax_kernel(
    const float* __restrict__ q_mask, const float* __restrict__ r_mask,
    const float* __restrict__ qr_cov,
    float* __restrict__ out_a, float* __restrict__ out_cov)
{
    const int b = blockIdx.x, tid = threadIdx.x;
    __shared__ float vals[L_];
    __shared__ float red[256];
    float m = -1e30f;
    for (int l = tid; l < L_; l += 256) {
        float v = g_logits[b * L_ + l];
        vals[l] = v;
        m = fmaxf(m, v);
    }
    red[tid] = m; __syncthreads();
    for (int s = 128; s > 0; s >>= 1) {
        if (tid < s) red[tid] = fmaxf(red[tid], red[tid + s]);
        __syncthreads();
    }
    const float mx = red[0]; __syncthreads();
    float sum = 0.f;
    for (int l = tid; l < L_; l += 256) {
        const float msk = (l < LQ_) ? q_mask[b * LQ_ + l]
                                    : r_mask[(size_t)b * (K_ * LR_) + (l - LQ_)];
        const float e = expf(vals[l] - mx) * msk;
        vals[l] = e;
        sum += e;
    }
    red[tid] = sum; __syncthreads();
    for (int s = 128; s > 0; s >>= 1) {
        if (tid < s) red[tid] += red[tid + s];
        __syncthreads();
    }
    const float inv = 1.f / red[0];
    for (int l = tid; l < L_; l += 256) {
        const float a = vals[l] * inv;
        out_a[b * L_ + l]   = a;
        out_cov[b * L_ + l] = qr_cov[b * L_ + l] + a;
    }
}

// ---------- c_t = sum_l (a*scale)[l] * base_row[l] ----------
__global__ __launch_bounds__(512) void ct_kernel(
    const float* __restrict__ h_q, const float* __restrict__ h_r,
    const float* __restrict__ a, float* __restrict__ c_t)
{
    const int b = blockIdx.x, h = threadIdx.x;
    __shared__ float w[128];
    float acc0 = 0.f, acc1 = 0.f;
    for (int l0 = 0; l0 < L_; l0 += 128) {
        __syncthreads();
        if (h < 128) {
            const int l = l0 + h;
            w[h] = a[b * L_ + l] * g_scale[b * L_ + l];
        }
        __syncthreads();
        const float* base = (l0 == 0)
            ? (h_q + (size_t)b * LQ_ * H_)
            : (h_r + ((size_t)b * (K_ * LR_) + (l0 - LQ_)) * H_);
#pragma unroll 4
        for (int j = 0; j < 128; j += 2) {
            acc0 = fmaf(w[j],     base[(size_t)j * H_ + h],       acc0);
            acc1 = fmaf(w[j + 1], base[(size_t)(j + 1) * H_ + h], acc1);
        }
    }
    c_t[b * H_ + h] = acc0 + acc1;
}

// ================================================================
extern "C" void kernel_launch(void* const* d_in, const int* in_sizes, int n_in,
                              void* d_out, int out_size)
{
    const float* h_q    = (const float*)d_in[0];
    const float* q_mask = (const float*)d_in[1];
    const float* h_r    = (const float*)d_in[2];
    const float* r_mask = (const float*)d_in[3];
    const float* s_t    = (const float*)d_in[4];
    const float* qr_cov = (const float*)d_in[5];
    const float* U_w    = (const float*)d_in[6];
    const float* Wc_w   = (const float*)d_in[7];
    const float* Ws_w   = (const float*)d_in[8];
    const float* Wqr_w  = (const float*)d_in[9];
    const float* Wqr_b  = (const float*)d_in[10];
    const float* Vr_w   = (const float*)d_in[11];

    float* out     = (float*)d_out;
    float* out_ct  = out;                       // [32, 512]
    float* out_a   = out + B_ * H_;             // [32, 2176]
    float* out_cov = out + B_ * H_ + B_ * L_;   // [32, 2176]

    // 1) hqU = h_q @ U^T         (dst 0 -> g_hqU)
    sgemm_nt_kernel<<<dim3(4, NQROWS / 128), 256>>>(h_q, U_w, 0);
    // 2) Yq = h_q @ Wqr^T (dst 1); Yr = h_r @ Wqr^T (dst 2)
    sgemm_nt_kernel<<<dim3(4, NQROWS / 128), 256>>>(h_q, Wqr_w, 1);
    sgemm_nt_kernel<<<dim3(4, NRROWS / 128), 256>>>(h_r, Wqr_w, 2);
    // 3) fused score maxes
    scores_kernel<<<dim3(4, BKT), 256>>>(h_r);
    // 4) softmaxes -> per-row scales
    alphaq_kernel<<<BKT, 128>>>();
    scaleq_kernel<<<B_, 128>>>(q_mask);
    alphar_kernel<<<BKT, 256>>>(r_mask);
    // 5) Ss = s_t @ Ws^T
    ss_kernel<<<B_, 512>>>(s_t, Ws_w);
    // 6) logits
    logits_kernel<<<(B_ * L_ * 32) / 256, 256>>>(qr_cov, Wqr_b, Wc_w, Vr_w);
    // 7) masked softmax -> a, new_cov
    final_softmax_kernel<<<B_, 256>>>(q_mask, r_mask, qr_cov, out_a, out_cov);
    // 8) c_t
    ct_kernel<<<B_, 512>>>(h_q, h_r, out_a, out_ct);
}

// round 7
// speedup vs baseline: 3.3534x; 3.3534x over previous
#include <cuda_runtime.h>
#include <cuda_bf16.h>
#include <cstdint>

// Problem constants
#define B_   32
#define K_   8
#define LQ_  128
#define LR_  256
#define H_   512
#define L_   2176          // LQ + K*LR
#define BKT  256           // B*K
#define NQROWS 4096        // B*LQ
#define NRROWS 65536       // B*K*LR
#define NCHUNK 17          // L / 128

// -------- scratch (device globals; resolved ONLY in device code) --------
__device__ __nv_bfloat16 g_hq_bf [NQROWS * H_];
__device__ __nv_bfloat16 g_hr_bf [(size_t)NRROWS * H_];
__device__ __nv_bfloat16 g_Uw_bf [H_ * H_];
__device__ __nv_bfloat16 g_Wqr_bf[H_ * H_];
__device__ __nv_bfloat16 g_hqU_bf[NQROWS * H_];
__device__ __nv_bfloat16 g_Yq_bf [NQROWS * H_];
__device__ __nv_bfloat16 g_Yr_bf [(size_t)NRROWS * H_];
__device__ float g_rowmax[BKT * 4 * LQ_];
__device__ float g_colmax[BKT * LR_];
__device__ float g_alpha_q[BKT * LQ_];
__device__ float g_scale[B_ * L_];
__device__ float g_Ss[B_ * H_];
__device__ float g_logits[B_ * L_];
__device__ float g_ct_part[B_ * NCHUNK * H_];

// Precise tanh, robust under --use_fast_math.
__device__ __forceinline__ float precise_tanh(float x) {
    const float ax = fabsf(x);
    const float e  = expf(-2.0f * ax);
    const float r  = (1.0f - e) / (1.0f + e);
    return copysignf(r, x);
}

__device__ __forceinline__ uint32_t smem_u32(const void* p) {
    return (uint32_t)__cvta_generic_to_shared(p);
}
__device__ __forceinline__ void ldmx4(uint32_t* r, uint32_t addr) {
    asm volatile("ldmatrix.sync.aligned.m8n8.x4.shared.b16 {%0,%1,%2,%3}, [%4];"
                 : "=r"(r[0]), "=r"(r[1]), "=r"(r[2]), "=r"(r[3]) : "r"(addr));
}
__device__ __forceinline__ void mma16816(float* d, const uint32_t* a, uint32_t b0, uint32_t b1) {
    asm volatile("mma.sync.aligned.m16n8k16.row.col.f32.bf16.bf16.f32 "
                 "{%0,%1,%2,%3}, {%4,%5,%6,%7}, {%8,%9}, {%0,%1,%2,%3};"
                 : "+f"(d[0]), "+f"(d[1]), "+f"(d[2]), "+f"(d[3])
                 : "r"(a[0]), "r"(a[1]), "r"(a[2]), "r"(a[3]), "r"(b0), "r"(b1));
}

// ---------- f32 -> bf16 converts (dst selected in device code) ----------
__global__ __launch_bounds__(256) void convert_kernel(const float* __restrict__ src,
                                                      int n4, int dst_sel)
{
    __nv_bfloat16* dst = (dst_sel == 0) ? g_hq_bf
                       : (dst_sel == 1) ? g_hr_bf
                       : (dst_sel == 2) ? g_Uw_bf : g_Wqr_bf;
    const int i = blockIdx.x * 256 + threadIdx.x;
    if (i >= n4) return;
    const float4 v = ((const float4*)src)[i];
    __nv_bfloat162* d2 = (__nv_bfloat162*)dst;
    d2[2 * i + 0] = __floats2bfloat162_rn(v.x, v.y);
    d2[2 * i + 1] = __floats2bfloat162_rn(v.z, v.w);
}

// ================================================================
// bf16 tensor GEMM: C[M,512](bf16) = A[M,512] @ W^T
// 128x128 tile, BK=32, 256 thr (8 warps, 4x2), warp tile 32x64.
// a_sel: 0=g_hq_bf 1=g_hr_bf; w_sel: 0=g_Uw_bf 1=g_Wqr_bf;
// c_sel: 0=g_hqU_bf 1=g_Yq_bf 2=g_Yr_bf
// ================================================================
__global__ __launch_bounds__(256) void hgemm_nt(int a_sel, int w_sel, int c_sel)
{
    const __nv_bfloat16* A = (a_sel == 0) ? g_hq_bf : g_hr_bf;
    const __nv_bfloat16* W = (w_sel == 0) ? g_Uw_bf : g_Wqr_bf;
    __nv_bfloat16* C = (c_sel == 0) ? g_hqU_bf : (c_sel == 1) ? g_Yq_bf : g_Yr_bf;

    __shared__ __align__(16) __nv_bfloat16 As[128][40];
    __shared__ __align__(16) __nv_bfloat16 Bs[128][40];

    const int tid = threadIdx.x, lane = tid & 31, warp = tid >> 5;
    const int wm = warp & 3, wn = warp >> 2;
    const size_t bm = (size_t)blockIdx.y * 128;
    const int    bn = blockIdx.x * 128;

    float acc[2][8][4];
#pragma unroll
    for (int i = 0; i < 2; i++)
#pragma unroll
        for (int j = 0; j < 8; j++)
#pragma unroll
            for (int v = 0; v < 4; v++) acc[i][j][v] = 0.f;

    const int srow = tid >> 2, scc = tid & 3;
    const __nv_bfloat16* Ag = A + (bm + srow) * H_ + scc * 8;
    const __nv_bfloat16* Wg = W + (size_t)(bn + srow) * H_ + scc * 8;

    for (int k0 = 0; k0 < H_; k0 += 32) {
        const int4 a0 = *(const int4*)(Ag + k0);
        const int4 a1 = *(const int4*)(Ag + (size_t)64 * H_ + k0);
        const int4 w0 = *(const int4*)(Wg + k0);
        const int4 w1 = *(const int4*)(Wg + (size_t)64 * H_ + k0);
        __syncthreads();
        *(int4*)&As[srow][scc * 8]      = a0;
        *(int4*)&As[srow + 64][scc * 8] = a1;
        *(int4*)&Bs[srow][scc * 8]      = w0;
        *(int4*)&Bs[srow + 64][scc * 8] = w1;
        __syncthreads();
#pragma unroll
        for (int ks = 0; ks < 2; ks++) {
            uint32_t afr[2][4];
#pragma unroll
            for (int mi = 0; mi < 2; mi++)
                ldmx4(afr[mi], smem_u32(&As[wm * 32 + mi * 16 + (lane & 15)][0])
                               + (lane >> 4) * 16 + ks * 32);
            uint32_t bfr[4][4];
#pragma unroll
            for (int nj = 0; nj < 4; nj++)
                ldmx4(bfr[nj], smem_u32(&Bs[wn * 64 + nj * 16 + (lane & 15)][0])
                               + (lane >> 4) * 16 + ks * 32);
#pragma unroll
            for (int mi = 0; mi < 2; mi++)
#pragma unroll
                for (int ni = 0; ni < 8; ni++)
                    mma16816(acc[mi][ni], afr[mi],
                             bfr[ni >> 1][ni & 1], bfr[ni >> 1][2 + (ni & 1)]);
        }
    }
#pragma unroll
    for (int mi = 0; mi < 2; mi++)
#pragma unroll
        for (int ni = 0; ni < 8; ni++) {
            const int row = wm * 32 + mi * 16 + (lane >> 2);
            const int col = bn + wn * 64 + ni * 8 + (lane & 3) * 2;
            *(__nv_bfloat162*)(C + (bm + row) * H_ + col) =
                __floats2bfloat162_rn(acc[mi][ni][0], acc[mi][ni][1]);
            *(__nv_bfloat162*)(C + (bm + row + 8) * H_ + col) =
                __floats2bfloat162_rn(acc[mi][ni][2], acc[mi][ni][3]);
        }
}

// ================================================================
// Scores (bf16 tensor): per (bk, rt): S = hqU[b] @ h_r[b,k,rt*64..]^T
// 128(q) x 64(r) tile; keep only row/col maxes -> tanh. Never stores S.
// 8 warps 4x2, warp tile 32x32.
// ================================================================
__global__ __launch_bounds__(256) void scores_kernel()
{
    const int bk = blockIdx.y, rt = blockIdx.x, b = bk >> 3;
    const __nv_bfloat16* A  = g_hqU_bf + (size_t)b * LQ_ * H_;
    const __nv_bfloat16* Bp = g_hr_bf + ((size_t)bk * LR_ + rt * 64) * H_;

    __shared__ __align__(16) __nv_bfloat16 As[128][40];
    __shared__ __align__(16) __nv_bfloat16 Bs[64][40];
    __shared__ float redQ[8][128];
    __shared__ float redC[32][64];

    const int tid = threadIdx.x, lane = tid & 31, warp = tid >> 5;
    const int wm = warp & 3, wn = warp >> 2;

    float acc[2][4][4];
#pragma unroll
    for (int i = 0; i < 2; i++)
#pragma unroll
        for (int j = 0; j < 4; j++)
#pragma unroll
            for (int v = 0; v < 4; v++) acc[i][j][v] = 0.f;

    const int srow = tid >> 2, scc = tid & 3;   // srow: 0..63
    const __nv_bfloat16* Ag = A + (size_t)srow * H_ + scc * 8;
    const __nv_bfloat16* Bg = Bp + (size_t)srow * H_ + scc * 8;

    for (int k0 = 0; k0 < H_; k0 += 32) {
        const int4 a0 = *(const int4*)(Ag + k0);
        const int4 a1 = *(const int4*)(Ag + (size_t)64 * H_ + k0);
        const int4 b0 = *(const int4*)(Bg + k0);
        __syncthreads();
        *(int4*)&As[srow][scc * 8]      = a0;
        *(int4*)&As[srow + 64][scc * 8] = a1;
        *(int4*)&Bs[srow][scc * 8]      = b0;
        __syncthreads();
#pragma unroll
        for (int ks = 0; ks < 2; ks++) {
            uint32_t afr[2][4];
#pragma unroll
            for (int mi = 0; mi < 2; mi++)
                ldmx4(afr[mi], smem_u32(&As[wm * 32 + mi * 16 + (lane & 15)][0])
                               + (lane >> 4) * 16 + ks * 32);
            uint32_t bfr[2][4];
#pragma unroll
            for (int nj = 0; nj < 2; nj++)
                ldmx4(bfr[nj], smem_u32(&Bs[wn * 32 + nj * 16 + (lane & 15)][0])
                               + (lane >> 4) * 16 + ks * 32);
#pragma unroll
            for (int mi = 0; mi < 2; mi++)
#pragma unroll
                for (int ni = 0; ni < 4; ni++)
                    mma16816(acc[mi][ni], afr[mi],
                             bfr[ni >> 1][ni & 1], bfr[ni >> 1][2 + (ni & 1)]);
        }
    }

    // per-thread row maxes (over its 8 cols) and col maxes (over its 4 rows)
    const int cidQ = (lane & 3) * 2 + wn;       // 0..7
    const int cidC = (lane >> 2) * 4 + wm;      // 0..31
#pragma unroll
    for (int mi = 0; mi < 2; mi++) {
        float rm0 = -1e30f, rm1 = -1e30f;
#pragma unroll
        for (int ni = 0; ni < 4; ni++) {
            rm0 = fmaxf(rm0, fmaxf(acc[mi][ni][0], acc[mi][ni][1]));
            rm1 = fmaxf(rm1, fmaxf(acc[mi][ni][2], acc[mi][ni][3]));
        }
        const int row0 = wm * 32 + mi * 16 + (lane >> 2);
        redQ[cidQ][row0]     = rm0;
        redQ[cidQ][row0 + 8] = rm1;
    }
#pragma unroll
    for (int ni = 0; ni < 4; ni++)
#pragma unroll
        for (int p = 0; p < 2; p++) {
            float cm = fmaxf(fmaxf(acc[0][ni][p], acc[0][ni][2 + p]),
                             fmaxf(acc[1][ni][p], acc[1][ni][2 + p]));
            const int col = wn * 32 + ni * 8 + (lane & 3) * 2 + p;
            redC[cidC][col] = cm;
        }
    __syncthreads();

    if (tid < 128) {
        float m = -1e30f;
#pragma unroll
        for (int g = 0; g < 8; g++) m = fmaxf(m, redQ[g][tid]);
        g_rowmax[((size_t)bk * 4 + rt) * LQ_ + tid] = precise_tanh(m);
    } else if (tid < 192) {
        const int r = tid - 128;
        float m = -1e30f;
#pragma unroll
        for (int g = 0; g < 32; g++) m = fmaxf(m, redC[g][r]);
        g_colmax[(size_t)bk * LR_ + rt * 64 + r] = precise_tanh(m);
    }
}

// ---------- softmax over q of rowmax -> alpha_q ----------
__global__ __launch_bounds__(128) void alphaq_kernel()
{
    const int bk = blockIdx.x;
    const int q  = threadIdx.x;
    float m = g_rowmax[(bk * 4 + 0) * LQ_ + q];
    m = fmaxf(m, g_rowmax[(bk * 4 + 1) * LQ_ + q]);
    m = fmaxf(m, g_rowmax[(bk * 4 + 2) * LQ_ + q]);
    m = fmaxf(m, g_rowmax[(bk * 4 + 3) * LQ_ + q]);
    __shared__ float red[128];
    red[q] = m; __syncthreads();
    for (int s = 64; s > 0; s >>= 1) {
        if (q < s) red[q] = fmaxf(red[q], red[q + s]);
        __syncthreads();
    }
    const float mx = red[0]; __syncthreads();
    const float e = expf(m - mx);
    red[q] = e; __syncthreads();
    for (int s = 64; s > 0; s >>= 1) {
        if (q < s) red[q] += red[q + s];
        __syncthreads();
    }
    g_alpha_q[bk * LQ_ + q] = e / red[0];
}

// ---------- scale for q rows: mean over k ----------
__global__ __launch_bounds__(128) void scaleq_kernel(const float* __restrict__ q_mask)
{
    const int b = blockIdx.x, q = threadIdx.x;
    float s = 0.f;
#pragma unroll
    for (int k = 0; k < K_; k++) s += g_alpha_q[(b * K_ + k) * LQ_ + q];
    g_scale[b * L_ + q] = s * 0.125f * q_mask[b * LQ_ + q];
}

// ---------- softmax over r of colmax -> scale for r rows ----------
__global__ __launch_bounds__(256) void alphar_kernel(const float* __restrict__ r_mask)
{
    const int bk = blockIdx.x;
    const int r  = threadIdx.x;
    const float m = g_colmax[(size_t)bk * LR_ + r];
    __shared__ float red[256];
    red[r] = m; __syncthreads();
    for (int s = 128; s > 0; s >>= 1) {
        if (r < s) red[r] = fmaxf(red[r], red[r + s]);
        __syncthreads();
    }
    const float mx = red[0]; __syncthreads();
    const float e = expf(m - mx);
    red[r] = e; __syncthreads();
    for (int s = 128; s > 0; s >>= 1) {
        if (r < s) red[r] += red[r + s];
        __syncthreads();
    }
    const int b = bk >> 3, k = bk & 7;
    g_scale[b * L_ + LQ_ + k * LR_ + r] = (e / red[0]) * r_mask[(size_t)bk * LR_ + r];
}

// ---------- Ss = s_t @ Ws^T ----------
__global__ __launch_bounds__(512) void ss_kernel(
    const float* __restrict__ s_t, const float* __restrict__ Ws)
{
    const int b = blockIdx.x, o = threadIdx.x;
    __shared__ float sv[H_];
    sv[o] = s_t[b * H_ + o];
    __syncthreads();
    const float* w = Ws + (size_t)o * H_;
    float acc = 0.f;
#pragma unroll 8
    for (int i = 0; i < H_; i++) acc = fmaf(sv[i], w[i], acc);
    g_Ss[b * H_ + o] = acc;
}

// ---------- logits: one warp per (b,l) row (Y in bf16) ----------
__global__ __launch_bounds__(256) void logits_kernel(
    const float* __restrict__ qr_cov, const float* __restrict__ Wqr_b,
    const float* __restrict__ Wc, const float* __restrict__ Vr)
{
    const int gw   = (blockIdx.x * 256 + threadIdx.x) >> 5;
    const int lane = threadIdx.x & 31;
    if (gw >= B_ * L_) return;
    const int b = gw / L_;
    const int l = gw - b * L_;
    const __nv_bfloat16* Y = (l < LQ_)
        ? (g_Yq_bf + ((size_t)b * LQ_ + l) * H_)
        : (g_Yr_bf + ((size_t)b * (K_ * LR_) + (l - LQ_)) * H_);
    const float sc  = g_scale[gw];
    const float cov = qr_cov[gw];
    const float* ss = g_Ss + b * H_;
    float acc = 0.f;
#pragma unroll
    for (int t = 0; t < 8; t++) {
        const int o = lane * 2 + t * 64;
        const __nv_bfloat162 y2 = *(const __nv_bfloat162*)(Y + o);
        const float2 ssv = *(const float2*)(ss + o);
        const float2 bv  = *(const float2*)(Wqr_b + o);
        const float2 wcv = *(const float2*)(Wc + o);
        const float2 vrv = *(const float2*)(Vr + o);
        const float d0 = ssv.x + sc * __bfloat162float(y2.x) + bv.x + cov * wcv.x;
        const float d1 = ssv.y + sc * __bfloat162float(y2.y) + bv.y + cov * wcv.y;
        acc += vrv.x * precise_tanh(d0) + vrv.y * precise_tanh(d1);
    }
#pragma unroll
    for (int s = 16; s > 0; s >>= 1) acc += __shfl_xor_sync(0xffffffffu, acc, s);
    if (lane == 0) g_logits[gw] = acc;
}

// ---------- final masked softmax over L, write a & new_cov ----------
__global__ __launch_bounds__(256) void final_softmax_kernel(
    const float* __restrict__ q_mask, const float* __restrict__ r_mask,
    const float* __restrict__ qr_cov,
    float* __restrict__ out_a, float* __restrict__ out_cov)
{
    const int b = blockIdx.x, tid = threadIdx.x;
    __shared__ float vals[L_];
    __shared__ float red[256];
    float m = -1e30f;
    for (int l = tid; l < L_; l += 256) {
        float v = g_logits[b * L_ + l];
        vals[l] = v;
        m = fmaxf(m, v);
    }
    red[tid] = m; __syncthreads();
    for (int s = 128; s > 0; s >>= 1) {
        if (tid < s) red[tid] = fmaxf(red[tid], red[tid + s]);
        __syncthreads();
    }
    const float mx = red[0]; __syncthreads();
    float sum = 0.f;
    for (int l = tid; l < L_; l += 256) {
        const float msk = (l < LQ_) ? q_mask[b * LQ_ + l]
                                    : r_mask[(size_t)b * (K_ * LR_) + (l - LQ_)];
        const float e = expf(vals[l] - mx) * msk;
        vals[l] = e;
        sum += e;
    }
    red[tid] = sum; __syncthreads();
    for (int s = 128; s > 0; s >>= 1) {
        if (tid < s) red[tid] += red[tid + s];
        __syncthreads();
    }
    const float inv = 1.f / red[0];
    for (int l = tid; l < L_; l += 256) {
        const float a = vals[l] * inv;
        out_a[b * L_ + l]   = a;
        out_cov[b * L_ + l] = qr_cov[b * L_ + l] + a;
    }
}

// ---------- c_t stage 1: partial sums per 128-l chunk ----------
__global__ __launch_bounds__(512) void ct_part_kernel(
    const float* __restrict__ h_q, const float* __restrict__ h_r,
    const float* __restrict__ a)
{
    const int b = blockIdx.x, c = blockIdx.y, h = threadIdx.x;
    __shared__ float w[128];
    if (h < 128) {
        const int l = c * 128 + h;
        w[h] = a[b * L_ + l] * g_scale[b * L_ + l];
    }
    __syncthreads();
    const float* base = (c == 0)
        ? (h_q + (size_t)b * LQ_ * H_)
        : (h_r + ((size_t)b * (K_ * LR_) + (c - 1) * 128) * H_);
    float acc0 = 0.f, acc1 = 0.f;
#pragma unroll 4
    for (int j = 0; j < 128; j += 2) {
        acc0 = fmaf(w[j],     base[(size_t)j * H_ + h],       acc0);
        acc1 = fmaf(w[j + 1], base[(size_t)(j + 1) * H_ + h], acc1);
    }
    g_ct_part[((size_t)b * NCHUNK + c) * H_ + h] = acc0 + acc1;
}

// ---------- c_t stage 2: reduce chunks (fixed order -> deterministic) ----------
__global__ __launch_bounds__(512) void ct_reduce_kernel(float* __restrict__ c_t)
{
    const int b = blockIdx.x, h = threadIdx.x;
    float s = 0.f;
#pragma unroll
    for (int c = 0; c < NCHUNK; c++)
        s += g_ct_part[((size_t)b * NCHUNK + c) * H_ + h];
    c_t[b * H_ + h] = s;
}

// ================================================================
extern "C" void kernel_launch(void* const* d_in, const int* in_sizes, int n_in,
                              void* d_out, int out_size)
{
    const float* h_q    = (const float*)d_in[0];
    const float* q_mask = (const float*)d_in[1];
    const float* h_r    = (const float*)d_in[2];
    const float* r_mask = (const float*)d_in[3];
    const float* s_t    = (const float*)d_in[4];
    const float* qr_cov = (const float*)d_in[5];
    const float* U_w    = (const float*)d_in[6];
    const float* Wc_w   = (const float*)d_in[7];
    const float* Ws_w   = (const float*)d_in[8];
    const float* Wqr_w  = (const float*)d_in[9];
    const float* Wqr_b  = (const float*)d_in[10];
    const float* Vr_w   = (const float*)d_in[11];

    float* out     = (float*)d_out;
    float* out_ct  = out;                       // [32, 512]
    float* out_a   = out + B_ * H_;             // [32, 2176]
    float* out_cov = out + B_ * H_ + B_ * L_;   // [32, 2176]

    // 0) converts to bf16
    const int nq4 = NQROWS * H_ / 4;            // 524288
    const int nr4 = NRROWS / 4 * H_;            // 8388608
    const int nw4 = H_ * H_ / 4;                // 65536
    convert_kernel<<<(nq4 + 255) / 256, 256>>>(h_q, nq4, 0);
    convert_kernel<<<(nr4 + 255) / 256, 256>>>(h_r, nr4, 1);
    convert_kernel<<<(nw4 + 255) / 256, 256>>>(U_w, nw4, 2);
    convert_kernel<<<(nw4 + 255) / 256, 256>>>(Wqr_w, nw4, 3);

    // 1) hqU = h_q @ U^T ; Yq = h_q @ Wqr^T ; Yr = h_r @ Wqr^T (bf16 tensor)
    hgemm_nt<<<dim3(4, NQROWS / 128), 256>>>(0, 0, 0);
    hgemm_nt<<<dim3(4, NQROWS / 128), 256>>>(0, 1, 1);
    hgemm_nt<<<dim3(4, NRROWS / 128), 256>>>(1, 1, 2);

    // 2) fused score maxes (bf16 tensor)
    scores_kernel<<<dim3(4, BKT), 256>>>();

    // 3) softmaxes -> per-row scales
    alphaq_kernel<<<BKT, 128>>>();
    scaleq_kernel<<<B_, 128>>>(q_mask);
    alphar_kernel<<<BKT, 256>>>(r_mask);

    // 4) Ss = s_t @ Ws^T
    ss_kernel<<<B_, 512>>>(s_t, Ws_w);

    // 5) logits
    logits_kernel<<<(B_ * L_ * 32) / 256, 256>>>(qr_cov, Wqr_b, Wc_w, Vr_w);

    // 6) masked softmax -> a, new_cov
    final_softmax_kernel<<<B_, 256>>>(q_mask, r_mask, qr_cov, out_a, out_cov);

    // 7) c_t (two-stage for occupancy)
    ct_part_kernel<<<dim3(B_, NCHUNK), 512>>>(h_q, h_r, out_a);
    ct_reduce_kernel<<<B_, 512>>>(out_ct);
}

// round 8
// speedup vs baseline: 5.0302x; 1.5000x over previous
#include <cuda_runtime.h>
#include <cuda_bf16.h>
#include <cstdint>

// Problem constants
#define B_   32
#define K_   8
#define LQ_  128
#define LR_  256
#define H_   512
#define L_   2176          // LQ + K*LR
#define BKT  256           // B*K
#define NQROWS 4096        // B*LQ
#define NRROWS 65536       // B*K*LR
#define NCHUNK 17          // L / 128

// -------- scratch (device globals; resolved ONLY in device code) --------
__device__ __nv_bfloat16 g_hq_bf [NQROWS * H_];
__device__ __nv_bfloat16 g_hr_bf [(size_t)NRROWS * H_];
__device__ __nv_bfloat16 g_Uw_bf [H_ * H_];
__device__ __nv_bfloat16 g_hqU_bf[NQROWS * H_];
__device__ float g_rowmax[BKT * 4 * LQ_];
__device__ float g_colmax[BKT * LR_];
__device__ float g_alpha_q[BKT * LQ_];
__device__ float g_scale[B_ * L_];
__device__ float g_Ss[B_ * H_];
__device__ float g_G[B_ * H_];       // Vr_o * (1 - tanh^2(c_o))
__device__ float g_WcG[B_];          // sum_o Wc_o * G_o
__device__ float g_u[B_ * H_];       // Wqr^T @ G_b
__device__ float g_logits[B_ * L_];
__device__ float g_ct_part[B_ * NCHUNK * H_];

// Precise tanh, robust under --use_fast_math.
__device__ __forceinline__ float precise_tanh(float x) {
    const float ax = fabsf(x);
    const float e  = expf(-2.0f * ax);
    const float r  = (1.0f - e) / (1.0f + e);
    return copysignf(r, x);
}

__device__ __forceinline__ uint32_t smem_u32(const void* p) {
    return (uint32_t)__cvta_generic_to_shared(p);
}
__device__ __forceinline__ void ldmx4(uint32_t* r, uint32_t addr) {
    asm volatile("ldmatrix.sync.aligned.m8n8.x4.shared.b16 {%0,%1,%2,%3}, [%4];"
                 : "=r"(r[0]), "=r"(r[1]), "=r"(r[2]), "=r"(r[3]) : "r"(addr));
}
__device__ __forceinline__ void mma16816(float* d, const uint32_t* a, uint32_t b0, uint32_t b1) {
    asm volatile("mma.sync.aligned.m16n8k16.row.col.f32.bf16.bf16.f32 "
                 "{%0,%1,%2,%3}, {%4,%5,%6,%7}, {%8,%9}, {%0,%1,%2,%3};"
                 : "+f"(d[0]), "+f"(d[1]), "+f"(d[2]), "+f"(d[3])
                 : "r"(a[0]), "r"(a[1]), "r"(a[2]), "r"(a[3]), "r"(b0), "r"(b1));
}

// ---------- f32 -> bf16 converts (dst selected in device code) ----------
__global__ __launch_bounds__(256) void convert_kernel(const float* __restrict__ src,
                                                      int n4, int dst_sel)
{
    __nv_bfloat16* dst = (dst_sel == 0) ? g_hq_bf
                       : (dst_sel == 1) ? g_hr_bf : g_Uw_bf;
    const int i = blockIdx.x * 256 + threadIdx.x;
    if (i >= n4) return;
    const float4 v = ((const float4*)src)[i];
    __nv_bfloat162* d2 = (__nv_bfloat162*)dst;
    d2[2 * i + 0] = __floats2bfloat162_rn(v.x, v.y);
    d2[2 * i + 1] = __floats2bfloat162_rn(v.z, v.w);
}

// ================================================================
// bf16 tensor GEMM: g_hqU_bf = g_hq_bf @ g_Uw_bf^T   (4096x512x512)
// 128x128 tile, BK=32, 256 thr (8 warps 4x2), warp tile 32x64.
// ================================================================
__global__ __launch_bounds__(256) void hgemm_hqU()
{
    const __nv_bfloat16* A = g_hq_bf;
    const __nv_bfloat16* W = g_Uw_bf;
    __nv_bfloat16* C = g_hqU_bf;

    __shared__ __align__(16) __nv_bfloat16 As[128][40];
    __shared__ __align__(16) __nv_bfloat16 Bs[128][40];

    const int tid = threadIdx.x, lane = tid & 31, warp = tid >> 5;
    const int wm = warp & 3, wn = warp >> 2;
    const size_t bm = (size_t)blockIdx.y * 128;
    const int    bn = blockIdx.x * 128;

    float acc[2][8][4];
#pragma unroll
    for (int i = 0; i < 2; i++)
#pragma unroll
        for (int j = 0; j < 8; j++)
#pragma unroll
            for (int v = 0; v < 4; v++) acc[i][j][v] = 0.f;

    const int srow = tid >> 2, scc = tid & 3;
    const __nv_bfloat16* Ag = A + (bm + srow) * H_ + scc * 8;
    const __nv_bfloat16* Wg = W + (size_t)(bn + srow) * H_ + scc * 8;

    for (int k0 = 0; k0 < H_; k0 += 32) {
        const int4 a0 = *(const int4*)(Ag + k0);
        const int4 a1 = *(const int4*)(Ag + (size_t)64 * H_ + k0);
        const int4 w0 = *(const int4*)(Wg + k0);
        const int4 w1 = *(const int4*)(Wg + (size_t)64 * H_ + k0);
        __syncthreads();
        *(int4*)&As[srow][scc * 8]      = a0;
        *(int4*)&As[srow + 64][scc * 8] = a1;
        *(int4*)&Bs[srow][scc * 8]      = w0;
        *(int4*)&Bs[srow + 64][scc * 8] = w1;
        __syncthreads();
#pragma unroll
        for (int ks = 0; ks < 2; ks++) {
            uint32_t afr[2][4];
#pragma unroll
            for (int mi = 0; mi < 2; mi++)
                ldmx4(afr[mi], smem_u32(&As[wm * 32 + mi * 16 + (lane & 15)][0])
                               + (lane >> 4) * 16 + ks * 32);
            uint32_t bfr[4][4];
#pragma unroll
            for (int nj = 0; nj < 4; nj++)
                ldmx4(bfr[nj], smem_u32(&Bs[wn * 64 + nj * 16 + (lane & 15)][0])
                               + (lane >> 4) * 16 + ks * 32);
#pragma unroll
            for (int mi = 0; mi < 2; mi++)
#pragma unroll
                for (int ni = 0; ni < 8; ni++)
                    mma16816(acc[mi][ni], afr[mi],
                             bfr[ni >> 1][ni & 1], bfr[ni >> 1][2 + (ni & 1)]);
        }
    }
#pragma unroll
    for (int mi = 0; mi < 2; mi++)
#pragma unroll
        for (int ni = 0; ni < 8; ni++) {
            const int row = wm * 32 + mi * 16 + (lane >> 2);
            const int col = bn + wn * 64 + ni * 8 + (lane & 3) * 2;
            *(__nv_bfloat162*)(C + (bm + row) * H_ + col) =
                __floats2bfloat162_rn(acc[mi][ni][0], acc[mi][ni][1]);
            *(__nv_bfloat162*)(C + (bm + row + 8) * H_ + col) =
                __floats2bfloat162_rn(acc[mi][ni][2], acc[mi][ni][3]);
        }
}

// ================================================================
// Scores (bf16 tensor): per (bk, rt): S = hqU[b] @ h_r[b,k,rt*64..]^T
// 128(q) x 64(r) tile; keep only row/col maxes -> tanh. Never stores S.
// ================================================================
__global__ __launch_bounds__(256) void scores_kernel()
{
    const int bk = blockIdx.y, rt = blockIdx.x, b = bk >> 3;
    const __nv_bfloat16* A  = g_hqU_bf + (size_t)b * LQ_ * H_;
    const __nv_bfloat16* Bp = g_hr_bf + ((size_t)bk * LR_ + rt * 64) * H_;

    __shared__ __align__(16) __nv_bfloat16 As[128][40];
    __shared__ __align__(16) __nv_bfloat16 Bs[64][40];
    __shared__ float redQ[8][128];
    __shared__ float redC[32][64];

    const int tid = threadIdx.x, lane = tid & 31, warp = tid >> 5;
    const int wm = warp & 3, wn = warp >> 2;

    float acc[2][4][4];
#pragma unroll
    for (int i = 0; i < 2; i++)
#pragma unroll
        for (int j = 0; j < 4; j++)
#pragma unroll
            for (int v = 0; v < 4; v++) acc[i][j][v] = 0.f;

    const int srow = tid >> 2, scc = tid & 3;   // srow: 0..63
    const __nv_bfloat16* Ag = A + (size_t)srow * H_ + scc * 8;
    const __nv_bfloat16* Bg = Bp + (size_t)srow * H_ + scc * 8;

    for (int k0 = 0; k0 < H_; k0 += 32) {
        const int4 a0 = *(const int4*)(Ag + k0);
        const int4 a1 = *(const int4*)(Ag + (size_t)64 * H_ + k0);
        const int4 b0 = *(const int4*)(Bg + k0);
        __syncthreads();
        *(int4*)&As[srow][scc * 8]      = a0;
        *(int4*)&As[srow + 64][scc * 8] = a1;
        *(int4*)&Bs[srow][scc * 8]      = b0;
        __syncthreads();
#pragma unroll
        for (int ks = 0; ks < 2; ks++) {
            uint32_t afr[2][4];
#pragma unroll
            for (int mi = 0; mi < 2; mi++)
                ldmx4(afr[mi], smem_u32(&As[wm * 32 + mi * 16 + (lane & 15)][0])
                               + (lane >> 4) * 16 + ks * 32);
            uint32_t bfr[2][4];
#pragma unroll
            for (int nj = 0; nj < 2; nj++)
                ldmx4(bfr[nj], smem_u32(&Bs[wn * 32 + nj * 16 + (lane & 15)][0])
                               + (lane >> 4) * 16 + ks * 32);
#pragma unroll
            for (int mi = 0; mi < 2; mi++)
#pragma unroll
                for (int ni = 0; ni < 4; ni++)
                    mma16816(acc[mi][ni], afr[mi],
                             bfr[ni >> 1][ni & 1], bfr[ni >> 1][2 + (ni & 1)]);
        }
    }

    const int cidQ = (lane & 3) * 2 + wn;       // 0..7
    const int cidC = (lane >> 2) * 4 + wm;      // 0..31
#pragma unroll
    for (int mi = 0; mi < 2; mi++) {
        float rm0 = -1e30f, rm1 = -1e30f;
#pragma unroll
        for (int ni = 0; ni < 4; ni++) {
            rm0 = fmaxf(rm0, fmaxf(acc[mi][ni][0], acc[mi][ni][1]));
            rm1 = fmaxf(rm1, fmaxf(acc[mi][ni][2], acc[mi][ni][3]));
        }
        const int row0 = wm * 32 + mi * 16 + (lane >> 2);
        redQ[cidQ][row0]     = rm0;
        redQ[cidQ][row0 + 8] = rm1;
    }
#pragma unroll
    for (int ni = 0; ni < 4; ni++)
#pragma unroll
        for (int p = 0; p < 2; p++) {
            float cm = fmaxf(fmaxf(acc[0][ni][p], acc[0][ni][2 + p]),
                             fmaxf(acc[1][ni][p], acc[1][ni][2 + p]));
            const int col = wn * 32 + ni * 8 + (lane & 3) * 2 + p;
            redC[cidC][col] = cm;
        }
    __syncthreads();

    if (tid < 128) {
        float m = -1e30f;
#pragma unroll
        for (int g = 0; g < 8; g++) m = fmaxf(m, redQ[g][tid]);
        g_rowmax[((size_t)bk * 4 + rt) * LQ_ + tid] = precise_tanh(m);
    } else if (tid < 192) {
        const int r = tid - 128;
        float m = -1e30f;
#pragma unroll
        for (int g = 0; g < 32; g++) m = fmaxf(m, redC[g][r]);
        g_colmax[(size_t)bk * LR_ + rt * 64 + r] = precise_tanh(m);
    }
}

// ---------- softmax over q of rowmax -> alpha_q ----------
__global__ __launch_bounds__(128) void alphaq_kernel()
{
    const int bk = blockIdx.x;
    const int q  = threadIdx.x;
    float m = g_rowmax[(bk * 4 + 0) * LQ_ + q];
    m = fmaxf(m, g_rowmax[(bk * 4 + 1) * LQ_ + q]);
    m = fmaxf(m, g_rowmax[(bk * 4 + 2) * LQ_ + q]);
    m = fmaxf(m, g_rowmax[(bk * 4 + 3) * LQ_ + q]);
    __shared__ float red[128];
    red[q] = m; __syncthreads();
    for (int s = 64; s > 0; s >>= 1) {
        if (q < s) red[q] = fmaxf(red[q], red[q + s]);
        __syncthreads();
    }
    const float mx = red[0]; __syncthreads();
    const float e = expf(m - mx);
    red[q] = e; __syncthreads();
    for (int s = 64; s > 0; s >>= 1) {
        if (q < s) red[q] += red[q + s];
        __syncthreads();
    }
    g_alpha_q[bk * LQ_ + q] = e / red[0];
}

// ---------- scale for q rows: mean over k ----------
__global__ __launch_bounds__(128) void scaleq_kernel(const float* __restrict__ q_mask)
{
    const int b = blockIdx.x, q = threadIdx.x;
    float s = 0.f;
#pragma unroll
    for (int k = 0; k < K_; k++) s += g_alpha_q[(b * K_ + k) * LQ_ + q];
    g_scale[b * L_ + q] = s * 0.125f * q_mask[b * LQ_ + q];
}

// ---------- softmax over r of colmax -> scale for r rows ----------
__global__ __launch_bounds__(256) void alphar_kernel(const float* __restrict__ r_mask)
{
    const int bk = blockIdx.x;
    const int r  = threadIdx.x;
    const float m = g_colmax[(size_t)bk * LR_ + r];
    __shared__ float red[256];
    red[r] = m; __syncthreads();
    for (int s = 128; s > 0; s >>= 1) {
        if (r < s) red[r] = fmaxf(red[r], red[r + s]);
        __syncthreads();
    }
    const float mx = red[0]; __syncthreads();
    const float e = expf(m - mx);
    red[r] = e; __syncthreads();
    for (int s = 128; s > 0; s >>= 1) {
        if (r < s) red[r] += red[r + s];
        __syncthreads();
    }
    const int b = bk >> 3, k = bk & 7;
    g_scale[b * L_ + LQ_ + k * LR_ + r] = (e / red[0]) * r_mask[(size_t)bk * LR_ + r];
}

// ---------- Ss = s_t @ Ws^T ----------
__global__ __launch_bounds__(512) void ss_kernel(
    const float* __restrict__ s_t, const float* __restrict__ Ws)
{
    const int b = blockIdx.x, o = threadIdx.x;
    __shared__ float sv[H_];
    sv[o] = s_t[b * H_ + o];
    __syncthreads();
    const float* w = Ws + (size_t)o * H_;
    float acc = 0.f;
#pragma unroll 8
    for (int i = 0; i < H_; i++) acc = fmaf(sv[i], w[i], acc);
    g_Ss[b * H_ + o] = acc;
}

// ---------- G_b[o] = Vr_o*(1 - tanh^2(c_o)),  WcG_b = sum_o Wc_o*G_b[o] ----------
__global__ __launch_bounds__(512) void g_kernel(
    const float* __restrict__ Wqr_b, const float* __restrict__ Wc,
    const float* __restrict__ Vr)
{
    const int b = blockIdx.x, o = threadIdx.x;
    const float c = g_Ss[b * H_ + o] + Wqr_b[o];
    const float t = precise_tanh(c);
    const float G = Vr[o] * (1.0f - t * t);
    g_G[b * H_ + o] = G;
    __shared__ float red[512];
    red[o] = G * Wc[o];
    __syncthreads();
    for (int s = 256; s > 0; s >>= 1) {
        if (o < s) red[o] += red[o + s];
        __syncthreads();
    }
    if (o == 0) g_WcG[b] = red[0];
}

// ---------- u_b = Wqr^T @ G_b  (per-batch GEMV) ----------
__global__ __launch_bounds__(128) void u_kernel(const float* __restrict__ Wqr)
{
    const int b = blockIdx.x;
    const int i = blockIdx.y * 128 + threadIdx.x;
    __shared__ float Gs[H_];
    for (int j = threadIdx.x; j < H_; j += 128) Gs[j] = g_G[b * H_ + j];
    __syncthreads();
    float acc = 0.f;
#pragma unroll 8
    for (int o = 0; o < H_; o++)
        acc = fmaf(Wqr[(size_t)o * H_ + i], Gs[o], acc);
    g_u[b * H_ + i] = acc;
}

// ---------- logits (linearized): logit_l = sc_l*(base_l . u_b) + cov_l*WcG_b ----------
__global__ __launch_bounds__(256) void logits_kernel(const float* __restrict__ qr_cov)
{
    const int b = blockIdx.x;
    const int warp = threadIdx.x >> 5, lane = threadIdx.x & 31;
    const int l = blockIdx.y * 8 + warp;           // 272*8 = 2176 rows
    __shared__ float su[H_];
    for (int j = threadIdx.x; j < H_; j += 256) su[j] = g_u[b * H_ + j];
    __syncthreads();

    const __nv_bfloat16* base = (l < LQ_)
        ? (g_hq_bf + ((size_t)b * LQ_ + l) * H_)
        : (g_hr_bf + ((size_t)b * (K_ * LR_) + (l - LQ_)) * H_);
    float acc = 0.f;
#pragma unroll
    for (int t = 0; t < 8; t++) {
        const int o = lane * 2 + t * 64;
        const __nv_bfloat162 v2 = *(const __nv_bfloat162*)(base + o);
        acc = fmaf(__bfloat162float(v2.x), su[o],     acc);
        acc = fmaf(__bfloat162float(v2.y), su[o + 1], acc);
    }
#pragma unroll
    for (int s = 16; s > 0; s >>= 1) acc += __shfl_xor_sync(0xffffffffu, acc, s);
    if (lane == 0) {
        const int gw = b * L_ + l;
        g_logits[gw] = g_scale[gw] * acc + qr_cov[gw] * g_WcG[b];
    }
}

// ---------- final masked softmax over L, write a & new_cov ----------
__global__ __launch_bounds__(256) void final_softmax_kernel(
    const float* __restrict__ q_mask, const float* __restrict__ r_mask,
    const float* __restrict__ qr_cov,
    float* __restrict__ out_a, float* __restrict__ out_cov)
{
    const int b = blockIdx.x, tid = threadIdx.x;
    __shared__ float vals[L_];
    __shared__ float red[256];
    float m = -1e30f;
    for (int l = tid; l < L_; l += 256) {
        float v = g_logits[b * L_ + l];
        vals[l] = v;
        m = fmaxf(m, v);
    }
    red[tid] = m; __syncthreads();
    for (int s = 128; s > 0; s >>= 1) {
        if (tid < s) red[tid] = fmaxf(red[tid], red[tid + s]);
        __syncthreads();
    }
    const float mx = red[0]; __syncthreads();
    float sum = 0.f;
    for (int l = tid; l < L_; l += 256) {
        const float msk = (l < LQ_) ? q_mask[b * LQ_ + l]
                                    : r_mask[(size_t)b * (K_ * LR_) + (l - LQ_)];
        const float e = expf(vals[l] - mx) * msk;
        vals[l] = e;
        sum += e;
    }
    red[tid] = sum; __syncthreads();
    for (int s = 128; s > 0; s >>= 1) {
        if (tid < s) red[tid] += red[tid + s];
        __syncthreads();
    }
    const float inv = 1.f / red[0];
    for (int l = tid; l < L_; l += 256) {
        const float a = vals[l] * inv;
        out_a[b * L_ + l]   = a;
        out_cov[b * L_ + l] = qr_cov[b * L_ + l] + a;
    }
}

// ---------- c_t stage 1: partial sums per 128-l chunk ----------
__global__ __launch_bounds__(512) void ct_part_kernel(
    const float* __restrict__ h_q, const float* __restrict__ h_r,
    const float* __restrict__ a)
{
    const int b = blockIdx.x, c = blockIdx.y, h = threadIdx.x;
    __shared__ float w[128];
    if (h < 128) {
        const int l = c * 128 + h;
        w[h] = a[b * L_ + l] * g_scale[b * L_ + l];
    }
    __syncthreads();
    const float* base = (c == 0)
        ? (h_q + (size_t)b * LQ_ * H_)
        : (h_r + ((size_t)b * (K_ * LR_) + (c - 1) * 128) * H_);
    float acc0 = 0.f, acc1 = 0.f;
#pragma unroll 4
    for (int j = 0; j < 128; j += 2) {
        acc0 = fmaf(w[j],     base[(size_t)j * H_ + h],       acc0);
        acc1 = fmaf(w[j + 1], base[(size_t)(j + 1) * H_ + h], acc1);
    }
    g_ct_part[((size_t)b * NCHUNK + c) * H_ + h] = acc0 + acc1;
}

// ---------- c_t stage 2: reduce chunks (fixed order -> deterministic) ----------
__global__ __launch_bounds__(512) void ct_reduce_kernel(float* __restrict__ c_t)
{
    const int b = blockIdx.x, h = threadIdx.x;
    float s = 0.f;
#pragma unroll
    for (int c = 0; c < NCHUNK; c++)
        s += g_ct_part[((size_t)b * NCHUNK + c) * H_ + h];
    c_t[b * H_ + h] = s;
}

// ================================================================
extern "C" void kernel_launch(void* const* d_in, const int* in_sizes, int n_in,
                              void* d_out, int out_size)
{
    const float* h_q    = (const float*)d_in[0];
    const float* q_mask = (const float*)d_in[1];
    const float* h_r    = (const float*)d_in[2];
    const float* r_mask = (const float*)d_in[3];
    const float* s_t    = (const float*)d_in[4];
    const float* qr_cov = (const float*)d_in[5];
    const float* U_w    = (const float*)d_in[6];
    const float* Wc_w   = (const float*)d_in[7];
    const float* Ws_w   = (const float*)d_in[8];
    const float* Wqr_w  = (const float*)d_in[9];
    const float* Wqr_b  = (const float*)d_in[10];
    const float* Vr_w   = (const float*)d_in[11];

    float* out     = (float*)d_out;
    float* out_ct  = out;                       // [32, 512]
    float* out_a   = out + B_ * H_;             // [32, 2176]
    float* out_cov = out + B_ * H_ + B_ * L_;   // [32, 2176]

    // 0) converts to bf16 (h_q, h_r, U only)
    const int nq4 = NQROWS * H_ / 4;            // 524288
    const int nr4 = NRROWS / 4 * H_;            // 8388608
    const int nw4 = H_ * H_ / 4;                // 65536
    convert_kernel<<<(nq4 + 255) / 256, 256>>>(h_q, nq4, 0);
    convert_kernel<<<(nr4 + 255) / 256, 256>>>(h_r, nr4, 1);
    convert_kernel<<<(nw4 + 255) / 256, 256>>>(U_w, nw4, 2);

    // 1) hqU = h_q @ U^T (bf16 tensor)
    hgemm_hqU<<<dim3(4, NQROWS / 128), 256>>>();

    // 2) fused score maxes (bf16 tensor)
    scores_kernel<<<dim3(4, BKT), 256>>>();

    // 3) softmaxes -> per-row scales
    alphaq_kernel<<<BKT, 128>>>();
    scaleq_kernel<<<B_, 128>>>(q_mask);
    alphar_kernel<<<BKT, 256>>>(r_mask);

    // 4) Ss = s_t @ Ws^T ; G ; u = Wqr^T G
    ss_kernel<<<B_, 512>>>(s_t, Ws_w);
    g_kernel<<<B_, 512>>>(Wqr_b, Wc_w, Vr_w);
    u_kernel<<<dim3(B_, 4), 128>>>(Wqr_w);

    // 5) logits (linearized: one dot per row instead of 512 tanh)
    logits_kernel<<<dim3(B_, L_ / 8), 256>>>(qr_cov);

    // 6) masked softmax -> a, new_cov
    final_softmax_kernel<<<B_, 256>>>(q_mask, r_mask, qr_cov, out_a, out_cov);

    // 7) c_t (two-stage for occupancy)
    ct_part_kernel<<<dim3(B_, NCHUNK), 512>>>(h_q, h_r, out_a);
    ct_reduce_kernel<<<B_, 512>>>(out_ct);
}

// round 9
// speedup vs baseline: 5.3425x; 1.0621x over previous
#include <cuda_runtime.h>
#include <cuda_bf16.h>
#include <cstdint>

// Problem constants
#define B_   32
#define K_   8
#define LQ_  128
#define LR_  256
#define H_   512
#define L_   2176          // LQ + K*LR
#define BKT  256           // B*K
#define NQROWS 4096        // B*LQ
#define NRROWS 65536       // B*K*LR
#define NCHUNK 17          // L / 128

// -------- scratch (device globals; resolved ONLY in device code) --------
__device__ __nv_bfloat16 g_hq_bf [NQROWS * H_];
__device__ __nv_bfloat16 g_hr_bf [(size_t)NRROWS * H_];
__device__ __nv_bfloat16 g_Uw_bf [H_ * H_];
__device__ __nv_bfloat16 g_hqU_bf[NQROWS * H_];
__device__ float g_rowmax[BKT * 2 * LQ_];
__device__ float g_colmax[BKT * LR_];
__device__ float g_alpha_q[BKT * LQ_];
__device__ float g_scale[B_ * L_];
__device__ float g_WcG[B_];          // sum_o Wc_o * G_o
__device__ float g_u[B_ * H_];       // Wqr^T @ G_b
__device__ float g_logits[B_ * L_];
__device__ float g_ct_part[B_ * NCHUNK * H_];

// Precise tanh, robust under --use_fast_math.
__device__ __forceinline__ float precise_tanh(float x) {
    const float ax = fabsf(x);
    const float e  = expf(-2.0f * ax);
    const float r  = (1.0f - e) / (1.0f + e);
    return copysignf(r, x);
}

__device__ __forceinline__ uint32_t smem_u32(const void* p) {
    return (uint32_t)__cvta_generic_to_shared(p);
}
__device__ __forceinline__ void ldmx4(uint32_t* r, uint32_t addr) {
    asm volatile("ldmatrix.sync.aligned.m8n8.x4.shared.b16 {%0,%1,%2,%3}, [%4];"
                 : "=r"(r[0]), "=r"(r[1]), "=r"(r[2]), "=r"(r[3]) : "r"(addr));
}
__device__ __forceinline__ void mma16816(float* d, const uint32_t* a, uint32_t b0, uint32_t b1) {
    asm volatile("mma.sync.aligned.m16n8k16.row.col.f32.bf16.bf16.f32 "
                 "{%0,%1,%2,%3}, {%4,%5,%6,%7}, {%8,%9}, {%0,%1,%2,%3};"
                 : "+f"(d[0]), "+f"(d[1]), "+f"(d[2]), "+f"(d[3])
                 : "r"(a[0]), "r"(a[1]), "r"(a[2]), "r"(a[3]), "r"(b0), "r"(b1));
}

// ---------- f32 -> bf16 converts (dst selected in device code) ----------
__global__ __launch_bounds__(256) void convert_kernel(const float* __restrict__ src,
                                                      int n4, int dst_sel)
{
    __nv_bfloat16* dst = (dst_sel == 0) ? g_hq_bf
                       : (dst_sel == 1) ? g_hr_bf : g_Uw_bf;
    const int i = blockIdx.x * 256 + threadIdx.x;
    if (i >= n4) return;
    const float4 v = ((const float4*)src)[i];
    __nv_bfloat162* d2 = (__nv_bfloat162*)dst;
    d2[2 * i + 0] = __floats2bfloat162_rn(v.x, v.y);
    d2[2 * i + 1] = __floats2bfloat162_rn(v.z, v.w);
}

// ================================================================
// bf16 tensor GEMM: g_hqU_bf = g_hq_bf @ g_Uw_bf^T   (4096x512x512)
// 128x128 tile, BK=32, 256 thr (8 warps 4x2), warp tile 32x64.
// ================================================================
__global__ __launch_bounds__(256) void hgemm_hqU()
{
    const __nv_bfloat16* A = g_hq_bf;
    const __nv_bfloat16* W = g_Uw_bf;
    __nv_bfloat16* C = g_hqU_bf;

    __shared__ __align__(16) __nv_bfloat16 As[128][40];
    __shared__ __align__(16) __nv_bfloat16 Bs[128][40];

    const int tid = threadIdx.x, lane = tid & 31, warp = tid >> 5;
    const int wm = warp & 3, wn = warp >> 2;
    const size_t bm = (size_t)blockIdx.y * 128;
    const int    bn = blockIdx.x * 128;

    float acc[2][8][4];
#pragma unroll
    for (int i = 0; i < 2; i++)
#pragma unroll
        for (int j = 0; j < 8; j++)
#pragma unroll
            for (int v = 0; v < 4; v++) acc[i][j][v] = 0.f;

    const int srow = tid >> 2, scc = tid & 3;
    const __nv_bfloat16* Ag = A + (bm + srow) * H_ + scc * 8;
    const __nv_bfloat16* Wg = W + (size_t)(bn + srow) * H_ + scc * 8;

    for (int k0 = 0; k0 < H_; k0 += 32) {
        const int4 a0 = *(const int4*)(Ag + k0);
        const int4 a1 = *(const int4*)(Ag + (size_t)64 * H_ + k0);
        const int4 w0 = *(const int4*)(Wg + k0);
        const int4 w1 = *(const int4*)(Wg + (size_t)64 * H_ + k0);
        __syncthreads();
        *(int4*)&As[srow][scc * 8]      = a0;
        *(int4*)&As[srow + 64][scc * 8] = a1;
        *(int4*)&Bs[srow][scc * 8]      = w0;
        *(int4*)&Bs[srow + 64][scc * 8] = w1;
        __syncthreads();
#pragma unroll
        for (int ks = 0; ks < 2; ks++) {
            uint32_t afr[2][4];
#pragma unroll
            for (int mi = 0; mi < 2; mi++)
                ldmx4(afr[mi], smem_u32(&As[wm * 32 + mi * 16 + (lane & 15)][0])
                               + (lane >> 4) * 16 + ks * 32);
            uint32_t bfr[4][4];
#pragma unroll
            for (int nj = 0; nj < 4; nj++)
                ldmx4(bfr[nj], smem_u32(&Bs[wn * 64 + nj * 16 + (lane & 15)][0])
                               + (lane >> 4) * 16 + ks * 32);
#pragma unroll
            for (int mi = 0; mi < 2; mi++)
#pragma unroll
                for (int ni = 0; ni < 8; ni++)
                    mma16816(acc[mi][ni], afr[mi],
                             bfr[ni >> 1][ni & 1], bfr[ni >> 1][2 + (ni & 1)]);
        }
    }
#pragma unroll
    for (int mi = 0; mi < 2; mi++)
#pragma unroll
        for (int ni = 0; ni < 8; ni++) {
            const int row = wm * 32 + mi * 16 + (lane >> 2);
            const int col = bn + wn * 64 + ni * 8 + (lane & 3) * 2;
            *(__nv_bfloat162*)(C + (bm + row) * H_ + col) =
                __floats2bfloat162_rn(acc[mi][ni][0], acc[mi][ni][1]);
            *(__nv_bfloat162*)(C + (bm + row + 8) * H_ + col) =
                __floats2bfloat162_rn(acc[mi][ni][2], acc[mi][ni][3]);
        }
}

// ================================================================
// Scores (bf16 tensor): per (bk, rt): S = hqU[b] @ h_r[b, k, rt*128..]^T
// 128(q) x 128(r) tile; keep only row/col maxes -> tanh. Never stores S.
// 8 warps 4x2, warp tile 32x64 (same shape as hgemm).
// ================================================================
__global__ __launch_bounds__(256) void scores_kernel()
{
    const int bk = blockIdx.y, rt = blockIdx.x, b = bk >> 3;
    const __nv_bfloat16* A  = g_hqU_bf + (size_t)b * LQ_ * H_;
    const __nv_bfloat16* Bp = g_hr_bf + ((size_t)bk * LR_ + rt * 128) * H_;

    __shared__ __align__(16) __nv_bfloat16 As[128][40];
    __shared__ __align__(16) __nv_bfloat16 Bs[128][40];
    __shared__ float redQ[8][128];
    __shared__ float redC[32][128];

    const int tid = threadIdx.x, lane = tid & 31, warp = tid >> 5;
    const int wm = warp & 3, wn = warp >> 2;

    float acc[2][8][4];
#pragma unroll
    for (int i = 0; i < 2; i++)
#pragma unroll
        for (int j = 0; j < 8; j++)
#pragma unroll
            for (int v = 0; v < 4; v++) acc[i][j][v] = 0.f;

    const int srow = tid >> 2, scc = tid & 3;   // srow: 0..63
    const __nv_bfloat16* Ag = A + (size_t)srow * H_ + scc * 8;
    const __nv_bfloat16* Bg = Bp + (size_t)srow * H_ + scc * 8;

    for (int k0 = 0; k0 < H_; k0 += 32) {
        const int4 a0 = *(const int4*)(Ag + k0);
        const int4 a1 = *(const int4*)(Ag + (size_t)64 * H_ + k0);
        const int4 b0 = *(const int4*)(Bg + k0);
        const int4 b1 = *(const int4*)(Bg + (size_t)64 * H_ + k0);
        __syncthreads();
        *(int4*)&As[srow][scc * 8]      = a0;
        *(int4*)&As[srow + 64][scc * 8] = a1;
        *(int4*)&Bs[srow][scc * 8]      = b0;
        *(int4*)&Bs[srow + 64][scc * 8] = b1;
        __syncthreads();
#pragma unroll
        for (int ks = 0; ks < 2; ks++) {
            uint32_t afr[2][4];
#pragma unroll
            for (int mi = 0; mi < 2; mi++)
                ldmx4(afr[mi], smem_u32(&As[wm * 32 + mi * 16 + (lane & 15)][0])
                               + (lane >> 4) * 16 + ks * 32);
            uint32_t bfr[4][4];
#pragma unroll
            for (int nj = 0; nj < 4; nj++)
                ldmx4(bfr[nj], smem_u32(&Bs[wn * 64 + nj * 16 + (lane & 15)][0])
                               + (lane >> 4) * 16 + ks * 32);
#pragma unroll
            for (int mi = 0; mi < 2; mi++)
#pragma unroll
                for (int ni = 0; ni < 8; ni++)
                    mma16816(acc[mi][ni], afr[mi],
                             bfr[ni >> 1][ni & 1], bfr[ni >> 1][2 + (ni & 1)]);
        }
    }

    // Row maxes: thread covers rows {wm*32+mi*16+(lane>>2), +8}, 16 vals each.
    const int cidQ = (lane & 3) * 2 + wn;       // 0..7 distinct per row
    const int cidC = (lane >> 2) * 4 + wm;      // 0..31 distinct per col
#pragma unroll
    for (int mi = 0; mi < 2; mi++) {
        float rm0 = -1e30f, rm1 = -1e30f;
#pragma unroll
        for (int ni = 0; ni < 8; ni++) {
            rm0 = fmaxf(rm0, fmaxf(acc[mi][ni][0], acc[mi][ni][1]));
            rm1 = fmaxf(rm1, fmaxf(acc[mi][ni][2], acc[mi][ni][3]));
        }
        const int row0 = wm * 32 + mi * 16 + (lane >> 2);
        redQ[cidQ][row0]     = rm0;
        redQ[cidQ][row0 + 8] = rm1;
    }
#pragma unroll
    for (int ni = 0; ni < 8; ni++)
#pragma unroll
        for (int p = 0; p < 2; p++) {
            float cm = fmaxf(fmaxf(acc[0][ni][p], acc[0][ni][2 + p]),
                             fmaxf(acc[1][ni][p], acc[1][ni][2 + p]));
            const int col = wn * 64 + ni * 8 + (lane & 3) * 2 + p;
            redC[cidC][col] = cm;
        }
    __syncthreads();

    if (tid < 128) {
        float m = -1e30f;
#pragma unroll
        for (int g = 0; g < 8; g++) m = fmaxf(m, redQ[g][tid]);
        g_rowmax[((size_t)bk * 2 + rt) * LQ_ + tid] = precise_tanh(m);
    } else {
        const int r = tid - 128;
        float m = -1e30f;
#pragma unroll
        for (int g = 0; g < 32; g++) m = fmaxf(m, redC[g][r]);
        g_colmax[(size_t)bk * LR_ + rt * 128 + r] = precise_tanh(m);
    }
}

// ---------- fused alpha softmaxes: r-scale (256) and alpha_q (128) ----------
__global__ __launch_bounds__(256) void alpha_kernel(const float* __restrict__ r_mask)
{
    const int bk = blockIdx.x, tid = threadIdx.x;
    __shared__ float red[256];

    // ---- r softmax over 256 colmax -> g_scale r part ----
    const float mr = g_colmax[(size_t)bk * LR_ + tid];
    red[tid] = mr; __syncthreads();
    for (int s = 128; s > 0; s >>= 1) {
        if (tid < s) red[tid] = fmaxf(red[tid], red[tid + s]);
        __syncthreads();
    }
    const float mxr = red[0]; __syncthreads();
    const float er = expf(mr - mxr);
    red[tid] = er; __syncthreads();
    for (int s = 128; s > 0; s >>= 1) {
        if (tid < s) red[tid] += red[tid + s];
        __syncthreads();
    }
    {
        const int b = bk >> 3, k = bk & 7;
        g_scale[b * L_ + LQ_ + k * LR_ + tid] =
            (er / red[0]) * r_mask[(size_t)bk * LR_ + tid];
    }
    __syncthreads();

    // ---- q softmax over 128 rowmax (2 rt slices) -> g_alpha_q ----
    const float mq = (tid < 128)
        ? fmaxf(g_rowmax[((size_t)bk * 2 + 0) * LQ_ + tid],
                g_rowmax[((size_t)bk * 2 + 1) * LQ_ + tid])
        : -1e30f;
    red[tid] = mq; __syncthreads();
    for (int s = 128; s > 0; s >>= 1) {
        if (tid < s) red[tid] = fmaxf(red[tid], red[tid + s]);
        __syncthreads();
    }
    const float mxq = red[0]; __syncthreads();
    const float eq = (tid < 128) ? expf(mq - mxq) : 0.f;
    red[tid] = eq; __syncthreads();
    for (int s = 128; s > 0; s >>= 1) {
        if (tid < s) red[tid] += red[tid + s];
        __syncthreads();
    }
    if (tid < 128) g_alpha_q[bk * LQ_ + tid] = eq / red[0];
}

// ---------- scale for q rows: mean over k ----------
__global__ __launch_bounds__(128) void scaleq_kernel(const float* __restrict__ q_mask)
{
    const int b = blockIdx.x, q = threadIdx.x;
    float s = 0.f;
#pragma unroll
    for (int k = 0; k < K_; k++) s += g_alpha_q[(b * K_ + k) * LQ_ + q];
    g_scale[b * L_ + q] = s * 0.125f * q_mask[b * LQ_ + q];
}

// ---------- fused: Ss -> G (smem) -> WcG, u = Wqr^T G ----------
__global__ __launch_bounds__(512) void ssgu_kernel(
    const float* __restrict__ s_t, const float* __restrict__ Ws,
    const float* __restrict__ Wqr, const float* __restrict__ Wqr_b,
    const float* __restrict__ Wc, const float* __restrict__ Vr)
{
    const int b = blockIdx.x, o = threadIdx.x;
    __shared__ float sv[H_];
    __shared__ float Gs[H_];
    __shared__ float red[512];

    sv[o] = s_t[b * H_ + o];
    __syncthreads();

    // Ss_o = Ws[o] . s_t[b]
    const float* w = Ws + (size_t)o * H_;
    float ss = 0.f;
#pragma unroll 8
    for (int i = 0; i < H_; i++) ss = fmaf(sv[i], w[i], ss);

    // G_o = Vr_o * (1 - tanh^2(Ss_o + b_o))
    const float t = precise_tanh(ss + Wqr_b[o]);
    const float G = Vr[o] * (1.0f - t * t);
    Gs[o] = G;
    red[o] = G * Wc[o];
    __syncthreads();
    for (int s = 256; s > 0; s >>= 1) {
        if (o < s) red[o] += red[o + s];
        __syncthreads();
    }
    if (o == 0) g_WcG[b] = red[0];

    // u_i = sum_o Wqr[o][i] * G_o   (coalesced across i = o here)
    float acc = 0.f;
#pragma unroll 8
    for (int oo = 0; oo < H_; oo++)
        acc = fmaf(Wqr[(size_t)oo * H_ + o], Gs[oo], acc);
    g_u[b * H_ + o] = acc;
}

// ---------- logits (linearized): logit_l = sc_l*(base_l . u_b) + cov_l*WcG_b ----------
__global__ __launch_bounds__(256) void logits_kernel(const float* __restrict__ qr_cov)
{
    const int b = blockIdx.x;
    const int warp = threadIdx.x >> 5, lane = threadIdx.x & 31;
    const int l = blockIdx.y * 8 + warp;           // 272*8 = 2176 rows
    __shared__ float su[H_];
    for (int j = threadIdx.x; j < H_; j += 256) su[j] = g_u[b * H_ + j];
    __syncthreads();

    const __nv_bfloat16* base = (l < LQ_)
        ? (g_hq_bf + ((size_t)b * LQ_ + l) * H_)
        : (g_hr_bf + ((size_t)b * (K_ * LR_) + (l - LQ_)) * H_);
    float acc = 0.f;
#pragma unroll
    for (int t = 0; t < 8; t++) {
        const int o = lane * 2 + t * 64;
        const __nv_bfloat162 v2 = *(const __nv_bfloat162*)(base + o);
        acc = fmaf(__bfloat162float(v2.x), su[o],     acc);
        acc = fmaf(__bfloat162float(v2.y), su[o + 1], acc);
    }
#pragma unroll
    for (int s = 16; s > 0; s >>= 1) acc += __shfl_xor_sync(0xffffffffu, acc, s);
    if (lane == 0) {
        const int gw = b * L_ + l;
        g_logits[gw] = g_scale[gw] * acc + qr_cov[gw] * g_WcG[b];
    }
}

// ---------- final masked softmax over L, write a & new_cov ----------
__global__ __launch_bounds__(256) void final_softmax_kernel(
    const float* __restrict__ q_mask, const float* __restrict__ r_mask,
    const float* __restrict__ qr_cov,
    float* __restrict__ out_a, float* __restrict__ out_cov)
{
    const int b = blockIdx.x, tid = threadIdx.x;
    __shared__ float vals[L_];
    __shared__ float red[256];
    float m = -1e30f;
    for (int l = tid; l < L_; l += 256) {
        float v = g_logits[b * L_ + l];
        vals[l] = v;
        m = fmaxf(m, v);
    }
    red[tid] = m; __syncthreads();
    for (int s = 128; s > 0; s >>= 1) {
        if (tid < s) red[tid] = fmaxf(red[tid], red[tid + s]);
        __syncthreads();
    }
    const float mx = red[0]; __syncthreads();
    float sum = 0.f;
    for (int l = tid; l < L_; l += 256) {
        const float msk = (l < LQ_) ? q_mask[b * LQ_ + l]
                                    : r_mask[(size_t)b * (K_ * LR_) + (l - LQ_)];
        const float e = expf(vals[l] - mx) * msk;
        vals[l] = e;
        sum += e;
    }
    red[tid] = sum; __syncthreads();
    for (int s = 128; s > 0; s >>= 1) {
        if (tid < s) red[tid] += red[tid + s];
        __syncthreads();
    }
    const float inv = 1.f / red[0];
    for (int l = tid; l < L_; l += 256) {
        const float a = vals[l] * inv;
        out_a[b * L_ + l]   = a;
        out_cov[b * L_ + l] = qr_cov[b * L_ + l] + a;
    }
}

// ---------- c_t stage 1: partial sums per 128-l chunk (fp32 inputs) ----------
__global__ __launch_bounds__(512) void ct_part_kernel(
    const float* __restrict__ h_q, const float* __restrict__ h_r,
    const float* __restrict__ a)
{
    const int b = blockIdx.x, c = blockIdx.y, h = threadIdx.x;
    __shared__ float w[128];
    if (h < 128) {
        const int l = c * 128 + h;
        w[h] = a[b * L_ + l] * g_scale[b * L_ + l];
    }
    __syncthreads();
    const float* base = (c == 0)
        ? (h_q + (size_t)b * LQ_ * H_)
        : (h_r + ((size_t)b * (K_ * LR_) + (c - 1) * 128) * H_);
    float acc0 = 0.f, acc1 = 0.f;
#pragma unroll 4
    for (int j = 0; j < 128; j += 2) {
        acc0 = fmaf(w[j],     base[(size_t)j * H_ + h],       acc0);
        acc1 = fmaf(w[j + 1], base[(size_t)(j + 1) * H_ + h], acc1);
    }
    g_ct_part[((size_t)b * NCHUNK + c) * H_ + h] = acc0 + acc1;
}

// ---------- c_t stage 2: reduce chunks (fixed order -> deterministic) ----------
__global__ __launch_bounds__(512) void ct_reduce_kernel(float* __restrict__ c_t)
{
    const int b = blockIdx.x, h = threadIdx.x;
    float s = 0.f;
#pragma unroll
    for (int c = 0; c < NCHUNK; c++)
        s += g_ct_part[((size_t)b * NCHUNK + c) * H_ + h];
    c_t[b * H_ + h] = s;
}

// ================================================================
extern "C" void kernel_launch(void* const* d_in, const int* in_sizes, int n_in,
                              void* d_out, int out_size)
{
    const float* h_q    = (const float*)d_in[0];
    const float* q_mask = (const float*)d_in[1];
    const float* h_r    = (const float*)d_in[2];
    const float* r_mask = (const float*)d_in[3];
    const float* s_t    = (const float*)d_in[4];
    const float* qr_cov = (const float*)d_in[5];
    const float* U_w    = (const float*)d_in[6];
    const float* Wc_w   = (const float*)d_in[7];
    const float* Ws_w   = (const float*)d_in[8];
    const float* Wqr_w  = (const float*)d_in[9];
    const float* Wqr_b  = (const float*)d_in[10];
    const float* Vr_w   = (const float*)d_in[11];

    float* out     = (float*)d_out;
    float* out_ct  = out;                       // [32, 512]
    float* out_a   = out + B_ * H_;             // [32, 2176]
    float* out_cov = out + B_ * H_ + B_ * L_;   // [32, 2176]

    // 0) converts to bf16 (h_q, h_r, U only)
    const int nq4 = NQROWS * H_ / 4;
    const int nr4 = NRROWS / 4 * H_;
    const int nw4 = H_ * H_ / 4;
    convert_kernel<<<(nq4 + 255) / 256, 256>>>(h_q, nq4, 0);
    convert_kernel<<<(nr4 + 255) / 256, 256>>>(h_r, nr4, 1);
    convert_kernel<<<(nw4 + 255) / 256, 256>>>(U_w, nw4, 2);

    // 1) hqU = h_q @ U^T (bf16 tensor)
    hgemm_hqU<<<dim3(4, NQROWS / 128), 256>>>();

    // 2) fused score maxes (bf16 tensor, 128x128 tiles)
    scores_kernel<<<dim3(2, BKT), 256>>>();

    // 3) fused alpha softmaxes -> per-row scales
    alpha_kernel<<<BKT, 256>>>(r_mask);
    scaleq_kernel<<<B_, 128>>>(q_mask);

    // 4) fused Ss -> G -> WcG, u
    ssgu_kernel<<<B_, 512>>>(s_t, Ws_w, Wqr_w, Wqr_b, Wc_w, Vr_w);

    // 5) logits (linearized)
    logits_kernel<<<dim3(B_, L_ / 8), 256>>>(qr_cov);

    // 6) masked softmax -> a, new_cov
    final_softmax_kernel<<<B_, 256>>>(q_mask, r_mask, qr_cov, out_a, out_cov);

    // 7) c_t (two-stage)
    ct_part_kernel<<<dim3(B_, NCHUNK), 512>>>(h_q, h_r, out_a);
    ct_reduce_kernel<<<B_, 512>>>(out_ct);
}